// round 5
// baseline (speedup 1.0000x reference)
#include <cuda_runtime.h>
#include <cuda_bf16.h>
#include <cstdint>

#define L_HOPS 5
#define D_DIM  32
#define E_MAX  131072

#define BLOCK   256
#define BPSM    6
#define NSM     148          // safe lower bound (GB300 has 152)
#define GRID    (NSM * BPSM) // 888 blocks, guaranteed co-resident at <=42 regs

// Precomputed dots[e][l] = <edge_vector[l], edge_attr[e]>  (2.6 MB, L2-resident)
__device__ float g_table[(size_t)E_MAX * L_HOPS];

// Epoch-based grid barrier counter (monotonic across graph replays)
__device__ unsigned long long g_bar = 0ULL;

// 1/max(len,1); len==0 -> 0 (sum is 0 anyway)
__constant__ float c_inv[8] = {0.0f, 1.0f, 0.5f, 1.0f / 3.0f, 0.25f, 0.2f, 0.0f, 0.0f};

// ---------------------------------------------------------------------------
// Fused kernel:
//   Phase A: all blocks compute dots[e][l] table (grid-stride over edges)
//   Barrier: device-wide epoch ticket barrier (all blocks resident by design)
//   Phase C: grid-stride over pair-quads; vectorized loads + predicated gathers
// ---------------------------------------------------------------------------
__global__ void __launch_bounds__(BLOCK, BPSM) fused_edge_encoding_kernel(
    const float* __restrict__ edge_attr,   // [E, 32]
    const float* __restrict__ edge_vector, // [5, 32]
    const int*   path_edges,               // [P, 5]
    const int*   path_len,                 // [P]
    float*       out,                      // [P]
    int E, int P)
{
    int tid = threadIdx.x;

    // ---- Phase A: dot-product table -------------------------------------
    __shared__ float sev[L_HOPS * D_DIM];
    if (tid < L_HOPS * D_DIM)
        sev[tid] = edge_vector[tid];
    __syncthreads();

    for (int e = blockIdx.x * BLOCK + tid; e < E; e += GRID * BLOCK) {
        const float4* row = reinterpret_cast<const float4*>(edge_attr + (size_t)e * D_DIM);
        float acc0 = 0.f, acc1 = 0.f, acc2 = 0.f, acc3 = 0.f, acc4 = 0.f;
#pragma unroll
        for (int i = 0; i < D_DIM / 4; i++) {
            float4 v = row[i];
#pragma unroll
            for (int c = 0; c < 4; c++) {
                float a = (c == 0) ? v.x : (c == 1) ? v.y : (c == 2) ? v.z : v.w;
                int d = i * 4 + c;
                acc0 = fmaf(a, sev[0 * D_DIM + d], acc0);
                acc1 = fmaf(a, sev[1 * D_DIM + d], acc1);
                acc2 = fmaf(a, sev[2 * D_DIM + d], acc2);
                acc3 = fmaf(a, sev[3 * D_DIM + d], acc3);
                acc4 = fmaf(a, sev[4 * D_DIM + d], acc4);
            }
        }
        float* t = g_table + (size_t)e * L_HOPS;
        t[0] = acc0; t[1] = acc1; t[2] = acc2; t[3] = acc3; t[4] = acc4;
    }

    // ---- Device-wide barrier (epoch ticket; all GRID blocks resident) ----
    __threadfence();
    __syncthreads();
    if (tid == 0) {
        unsigned long long ticket = atomicAdd(&g_bar, 1ULL);
        unsigned long long target = (ticket / GRID + 1ULL) * GRID;
        volatile unsigned long long* bar = &g_bar;
        while (*bar < target) { /* spin */ }
    }
    __syncthreads();
    __threadfence();

    // ---- Phase C: pair reduction (4 pairs per thread, grid-stride) -------
    int Pq = P >> 2;  // quads
    const int4* gpe = reinterpret_cast<const int4*>(path_edges);
    const int4* gpl = reinterpret_cast<const int4*>(path_len);
    float4*     go  = reinterpret_cast<float4*>(out);

    for (int t = blockIdx.x * BLOCK + tid; t < Pq; t += GRID * BLOCK) {
        // 4 pairs: 20 indices = 5 x int4 (80 B per quad, 16B-aligned)
        const int4* pe = gpe + (size_t)t * 5;
        int4 a  = pe[0];
        int4 b  = pe[1];
        int4 c  = pe[2];
        int4 d  = pe[3];
        int4 e4 = pe[4];
        int4 ln = gpl[t];

        // Predicated gathers (plain loads: table written in this kernel).
        float v00 = (ln.x > 0) ? g_table[(unsigned)a.x  * 5u + 0u] : 0.f;
        float v01 = (ln.x > 1) ? g_table[(unsigned)a.y  * 5u + 1u] : 0.f;
        float v02 = (ln.x > 2) ? g_table[(unsigned)a.z  * 5u + 2u] : 0.f;
        float v03 = (ln.x > 3) ? g_table[(unsigned)a.w  * 5u + 3u] : 0.f;
        float v04 = (ln.x > 4) ? g_table[(unsigned)b.x  * 5u + 4u] : 0.f;

        float v10 = (ln.y > 0) ? g_table[(unsigned)b.y  * 5u + 0u] : 0.f;
        float v11 = (ln.y > 1) ? g_table[(unsigned)b.z  * 5u + 1u] : 0.f;
        float v12 = (ln.y > 2) ? g_table[(unsigned)b.w  * 5u + 2u] : 0.f;
        float v13 = (ln.y > 3) ? g_table[(unsigned)c.x  * 5u + 3u] : 0.f;
        float v14 = (ln.y > 4) ? g_table[(unsigned)c.y  * 5u + 4u] : 0.f;

        float v20 = (ln.z > 0) ? g_table[(unsigned)c.z  * 5u + 0u] : 0.f;
        float v21 = (ln.z > 1) ? g_table[(unsigned)c.w  * 5u + 1u] : 0.f;
        float v22 = (ln.z > 2) ? g_table[(unsigned)d.x  * 5u + 2u] : 0.f;
        float v23 = (ln.z > 3) ? g_table[(unsigned)d.y  * 5u + 3u] : 0.f;
        float v24 = (ln.z > 4) ? g_table[(unsigned)d.z  * 5u + 4u] : 0.f;

        float v30 = (ln.w > 0) ? g_table[(unsigned)d.w  * 5u + 0u] : 0.f;
        float v31 = (ln.w > 1) ? g_table[(unsigned)e4.x * 5u + 1u] : 0.f;
        float v32 = (ln.w > 2) ? g_table[(unsigned)e4.y * 5u + 2u] : 0.f;
        float v33 = (ln.w > 3) ? g_table[(unsigned)e4.z * 5u + 3u] : 0.f;
        float v34 = (ln.w > 4) ? g_table[(unsigned)e4.w * 5u + 4u] : 0.f;

        float4 r;
        r.x = (((v00 + v01) + (v02 + v03)) + v04) * c_inv[ln.x & 7];
        r.y = (((v10 + v11) + (v12 + v13)) + v14) * c_inv[ln.y & 7];
        r.z = (((v20 + v21) + (v22 + v23)) + v24) * c_inv[ln.z & 7];
        r.w = (((v30 + v31) + (v32 + v33)) + v34) * c_inv[ln.w & 7];
        go[t] = r;
    }

    // Scalar tail for P % 4 (not hit for N=1024)
    for (int p = (Pq << 2) + blockIdx.x * BLOCK + tid; p < P; p += GRID * BLOCK) {
        int len = path_len[p];
        const int* row = path_edges + (size_t)p * L_HOPS;
        float s = 0.f;
#pragma unroll
        for (int l = 0; l < L_HOPS; l++)
            s += (len > l) ? g_table[(unsigned)row[l] * 5u + (unsigned)l] : 0.f;
        out[p] = s * c_inv[len & 7];
    }
}

// ---------------------------------------------------------------------------
// Inputs: x[N,32], edge_attr[E,32], edge_vector[5,32],
//         path_edges[P,5] (int32), path_len[P] (int32)  -> out float32 [P]
// ---------------------------------------------------------------------------
extern "C" void kernel_launch(void* const* d_in, const int* in_sizes, int n_in,
                              void* d_out, int out_size)
{
    const float* edge_attr   = (const float*)d_in[1];
    const float* edge_vector = (const float*)d_in[2];
    const int*   path_edges  = (const int*)d_in[3];
    const int*   path_len    = (const int*)d_in[4];
    float*       out         = (float*)d_out;

    int E = in_sizes[1] / D_DIM;
    int P = out_size;

    fused_edge_encoding_kernel<<<GRID, BLOCK>>>(
        edge_attr, edge_vector, path_edges, path_len, out, E, P);
}

// round 6
// speedup vs baseline: 2.0550x; 2.0550x over previous
#include <cuda_runtime.h>
#include <cuda_bf16.h>
#include <cstdint>

#define L_HOPS 5
#define D_DIM  32
#define E_MAX  131072

// Precomputed dots[e][l] = <edge_vector[l], edge_attr[e]>  (2.6 MB, L2-resident)
__device__ float g_table[(size_t)E_MAX * L_HOPS];

// 1/max(len,1); len==0 -> 0 (sum is 0 anyway)
__constant__ float c_inv[8] = {0.0f, 1.0f, 0.5f, 1.0f / 3.0f, 0.25f, 0.2f, 0.0f, 0.0f};

// ---------------------------------------------------------------------------
// Kernel 1: per-(edge, hop) dot products. One thread per edge (128 B row).
// Fires the programmatic-launch trigger once its table writes are issued.
// ---------------------------------------------------------------------------
__global__ void __launch_bounds__(256) precompute_dots_kernel(
    const float* __restrict__ edge_attr,   // [E, 32]
    const float* __restrict__ edge_vector, // [5, 32]
    int E)
{
    __shared__ float sev[L_HOPS * D_DIM];
    if (threadIdx.x < L_HOPS * D_DIM)
        sev[threadIdx.x] = edge_vector[threadIdx.x];
    __syncthreads();

    int e = blockIdx.x * blockDim.x + threadIdx.x;
    if (e < E) {
        const float4* row = reinterpret_cast<const float4*>(edge_attr + (size_t)e * D_DIM);

        float acc0 = 0.f, acc1 = 0.f, acc2 = 0.f, acc3 = 0.f, acc4 = 0.f;
#pragma unroll
        for (int i = 0; i < D_DIM / 4; i++) {
            float4 v = row[i];
#pragma unroll
            for (int c = 0; c < 4; c++) {
                float a = (c == 0) ? v.x : (c == 1) ? v.y : (c == 2) ? v.z : v.w;
                int d = i * 4 + c;
                acc0 = fmaf(a, sev[0 * D_DIM + d], acc0);
                acc1 = fmaf(a, sev[1 * D_DIM + d], acc1);
                acc2 = fmaf(a, sev[2 * D_DIM + d], acc2);
                acc3 = fmaf(a, sev[3 * D_DIM + d], acc3);
                acc4 = fmaf(a, sev[4 * D_DIM + d], acc4);
            }
        }

        float* t = g_table + (size_t)e * L_HOPS;
        t[0] = acc0; t[1] = acc1; t[2] = acc2; t[3] = acc3; t[4] = acc4;
    }

    // Allow the dependent pair kernel's gather phase to proceed.
    cudaTriggerProgrammaticLaunchCompletion();
}

// ---------------------------------------------------------------------------
// Kernel 2 (PDL consumer): 4 pairs per thread.
//   Front half: stream indices + lens (independent of the table).
//   cudaGridDependencySynchronize(): wait for precompute completion.
//   Back half: predicated gathers + masked mean.
// ---------------------------------------------------------------------------
__global__ void __launch_bounds__(256) pair_reduce_kernel4(
    const int* __restrict__ path_edges,  // [P, 5]
    const int* __restrict__ path_len,    // [P]
    float* __restrict__ out,             // [P]
    int Pq)                              // P / 4
{
    int t = blockIdx.x * blockDim.x + threadIdx.x;
    if (t >= Pq) {
        cudaGridDependencySynchronize();
        return;
    }

    // 4 pairs: 20 indices = 5 x int4 (80 B, 16B-aligned), len = 1 x int4.
    const int4* pe = reinterpret_cast<const int4*>(path_edges) + (size_t)t * 5;
    int4 a  = __ldg(pe + 0);
    int4 b  = __ldg(pe + 1);
    int4 c  = __ldg(pe + 2);
    int4 d  = __ldg(pe + 3);
    int4 e4 = __ldg(pe + 4);
    int4 ln = __ldg(reinterpret_cast<const int4*>(path_len) + t);

    // Table is now guaranteed complete.
    cudaGridDependencySynchronize();

    float v00 = (ln.x > 0) ? __ldg(&g_table[(unsigned)a.x  * 5u + 0u]) : 0.f;
    float v01 = (ln.x > 1) ? __ldg(&g_table[(unsigned)a.y  * 5u + 1u]) : 0.f;
    float v02 = (ln.x > 2) ? __ldg(&g_table[(unsigned)a.z  * 5u + 2u]) : 0.f;
    float v03 = (ln.x > 3) ? __ldg(&g_table[(unsigned)a.w  * 5u + 3u]) : 0.f;
    float v04 = (ln.x > 4) ? __ldg(&g_table[(unsigned)b.x  * 5u + 4u]) : 0.f;

    float v10 = (ln.y > 0) ? __ldg(&g_table[(unsigned)b.y  * 5u + 0u]) : 0.f;
    float v11 = (ln.y > 1) ? __ldg(&g_table[(unsigned)b.z  * 5u + 1u]) : 0.f;
    float v12 = (ln.y > 2) ? __ldg(&g_table[(unsigned)b.w  * 5u + 2u]) : 0.f;
    float v13 = (ln.y > 3) ? __ldg(&g_table[(unsigned)c.x  * 5u + 3u]) : 0.f;
    float v14 = (ln.y > 4) ? __ldg(&g_table[(unsigned)c.y  * 5u + 4u]) : 0.f;

    float v20 = (ln.z > 0) ? __ldg(&g_table[(unsigned)c.z  * 5u + 0u]) : 0.f;
    float v21 = (ln.z > 1) ? __ldg(&g_table[(unsigned)c.w  * 5u + 1u]) : 0.f;
    float v22 = (ln.z > 2) ? __ldg(&g_table[(unsigned)d.x  * 5u + 2u]) : 0.f;
    float v23 = (ln.z > 3) ? __ldg(&g_table[(unsigned)d.y  * 5u + 3u]) : 0.f;
    float v24 = (ln.z > 4) ? __ldg(&g_table[(unsigned)d.z  * 5u + 4u]) : 0.f;

    float v30 = (ln.w > 0) ? __ldg(&g_table[(unsigned)d.w  * 5u + 0u]) : 0.f;
    float v31 = (ln.w > 1) ? __ldg(&g_table[(unsigned)e4.x * 5u + 1u]) : 0.f;
    float v32 = (ln.w > 2) ? __ldg(&g_table[(unsigned)e4.y * 5u + 2u]) : 0.f;
    float v33 = (ln.w > 3) ? __ldg(&g_table[(unsigned)e4.z * 5u + 3u]) : 0.f;
    float v34 = (ln.w > 4) ? __ldg(&g_table[(unsigned)e4.w * 5u + 4u]) : 0.f;

    float4 r;
    r.x = (((v00 + v01) + (v02 + v03)) + v04) * c_inv[ln.x & 7];
    r.y = (((v10 + v11) + (v12 + v13)) + v14) * c_inv[ln.y & 7];
    r.z = (((v20 + v21) + (v22 + v23)) + v24) * c_inv[ln.z & 7];
    r.w = (((v30 + v31) + (v32 + v33)) + v34) * c_inv[ln.w & 7];
    reinterpret_cast<float4*>(out)[t] = r;
}

// Scalar fallback for P not divisible by 4 (not hit for N=1024).
__global__ void pair_reduce_tail(
    const int* __restrict__ path_edges,
    const int* __restrict__ path_len,
    float* __restrict__ out,
    int start, int P)
{
    int p = start + blockIdx.x * blockDim.x + threadIdx.x;
    if (p >= P) return;
    int len = path_len[p];
    const int* row = path_edges + (size_t)p * L_HOPS;
    float s = 0.f;
#pragma unroll
    for (int l = 0; l < L_HOPS; l++)
        s += (len > l) ? __ldg(&g_table[(size_t)row[l] * L_HOPS + l]) : 0.f;
    out[p] = s * c_inv[len & 7];
}

// ---------------------------------------------------------------------------
// Inputs: x[N,32], edge_attr[E,32], edge_vector[5,32],
//         path_edges[P,5] (int32), path_len[P] (int32)  -> out float32 [P]
// ---------------------------------------------------------------------------
extern "C" void kernel_launch(void* const* d_in, const int* in_sizes, int n_in,
                              void* d_out, int out_size)
{
    const float* edge_attr   = (const float*)d_in[1];
    const float* edge_vector = (const float*)d_in[2];
    const int*   path_edges  = (const int*)d_in[3];
    const int*   path_len    = (const int*)d_in[4];
    float*       out         = (float*)d_out;

    int E = in_sizes[1] / D_DIM;
    int P = out_size;

    // Producer
    {
        int threads = 256;
        int blocks = (E + threads - 1) / threads;
        precompute_dots_kernel<<<blocks, threads>>>(edge_attr, edge_vector, E);
    }

    // Consumer with Programmatic Dependent Launch: starts while the producer
    // is still running; gathers wait on cudaGridDependencySynchronize().
    int Pq = P / 4;
    if (Pq > 0) {
        int threads = 256;
        int blocks = (Pq + threads - 1) / threads;

        cudaLaunchConfig_t cfg = {};
        cfg.gridDim  = dim3((unsigned)blocks, 1, 1);
        cfg.blockDim = dim3((unsigned)threads, 1, 1);
        cfg.dynamicSmemBytes = 0;
        cfg.stream = 0;  // legacy default stream (what the harness captures)

        cudaLaunchAttribute attr[1];
        attr[0].id = cudaLaunchAttributeProgrammaticStreamSerialization;
        attr[0].val.programmaticStreamSerializationAllowed = 1;
        cfg.attrs = attr;
        cfg.numAttrs = 1;

        cudaLaunchKernelEx(&cfg, pair_reduce_kernel4, path_edges, path_len, out, Pq);
    }

    int done = Pq * 4;
    if (done < P) {
        int rem = P - done;
        pair_reduce_tail<<<(rem + 255) / 256, 256>>>(path_edges, path_len, out, done, P);
    }
}